// round 1
// baseline (speedup 1.0000x reference)
#include <cuda_runtime.h>
#include <math.h>

#define HH 512
#define WW 512
#define NB 64
#define KK 31
#define PD 15

// 64 MB scratch for vertical box sums (allocation-free rule: __device__ global)
__device__ float g_colsum[(size_t)NB * HH * WW];
__device__ double g_inter[NB];
__device__ double g_union[NB];

__global__ void zero_acc_kernel() {
    int t = threadIdx.x;
    if (t < NB) { g_inter[t] = 0.0; g_union[t] = 0.0; }
}

// Vertical 31-tap box sum of mask (zero pad), strips of 128 rows.
// grid: (WW/256, 4, NB), block: 256
__global__ void vpass_kernel(const float* __restrict__ mask) {
    int c = blockIdx.x * blockDim.x + threadIdx.x;   // 0..511
    int r0 = blockIdx.y * 128;                        // strip start row
    int b  = blockIdx.z;
    const float* m = mask + ((size_t)b * HH) * WW;
    float* out = g_colsum + ((size_t)b * HH) * WW;

    float s = 0.f;
    // init: rows [r0-15, r0+14]
    #pragma unroll 4
    for (int r = r0 - PD; r < r0 + PD; ++r) {
        if (r >= 0 && r < HH) s += m[(size_t)r * WW + c];
    }
    #pragma unroll 4
    for (int r = r0; r < r0 + 128; ++r) {
        int ra = r + PD;
        if (ra < HH) s += m[(size_t)ra * WW + c];
        out[(size_t)r * WW + c] = s;                  // window [r-15, r+15]
        int rs = r - PD;
        if (rs >= 0) s -= m[(size_t)rs * WW + c];
    }
}

// Horizontal 31-tap box sum on colsum row + fused weit/sigmoid/reduction.
// grid: (HH, NB), block: 128 (each thread owns 4 consecutive columns)
__global__ void hpass_kernel(const float* __restrict__ pred,
                             const float* __restrict__ mask) {
    __shared__ float row[WW + 32];   // 16 zero halo each side
    __shared__ float s_i[4], s_u[4];

    int r = blockIdx.x;
    int b = blockIdx.y;
    int t = threadIdx.x;             // 0..127
    const size_t base = ((size_t)b * HH + r) * WW;

    if (t < 16) { row[t] = 0.f; row[WW + 16 + t] = 0.f; }
    // load colsum row (coalesced float4)
    float4 cs = reinterpret_cast<const float4*>(g_colsum + base)[t];
    reinterpret_cast<float4*>(row + 16)[t] = cs;
    float4 m4 = reinterpret_cast<const float4*>(mask + base)[t];
    float4 p4 = reinterpret_cast<const float4*>(pred + base)[t];
    __syncthreads();

    int c0 = t * 4;
    // window for column c is smem[c+1 .. c+31]
    float s = 0.f;
    #pragma unroll
    for (int j = 0; j < KK; ++j) s += row[c0 + 1 + j];

    const float inv = 1.0f / (float)(KK * KK);
    float fi = 0.f, fu = 0.f;
    float mk[4] = {m4.x, m4.y, m4.z, m4.w};
    float pr[4] = {p4.x, p4.y, p4.z, p4.w};
    #pragma unroll
    for (int q = 0; q < 4; ++q) {
        int c = c0 + q;
        float avg  = s * inv;
        float weit = fmaf(5.f, fabsf(avg - mk[q]), 1.f);
        float p    = __frcp_rn(1.f + __expf(-pr[q]));
        fi = fmaf(p * mk[q], weit, fi);
        fu = fmaf(p + mk[q], weit, fu);
        // slide: add c+16 (smem c+32), remove c-15 (smem c+1)
        s += row[c + 32] - row[c + 1];
    }

    // block reduce 128 -> 1
    #pragma unroll
    for (int o = 16; o; o >>= 1) {
        fi += __shfl_down_sync(0xffffffffu, fi, o);
        fu += __shfl_down_sync(0xffffffffu, fu, o);
    }
    int wid = t >> 5, lane = t & 31;
    if (lane == 0) { s_i[wid] = fi; s_u[wid] = fu; }
    __syncthreads();
    if (t == 0) {
        float ti = s_i[0] + s_i[1] + s_i[2] + s_i[3];
        float tu = s_u[0] + s_u[1] + s_u[2] + s_u[3];
        atomicAdd(&g_inter[b], (double)ti);
        atomicAdd(&g_union[b], (double)tu);
    }
}

__global__ void finalize_kernel(float* __restrict__ out) {
    int t = threadIdx.x;   // 64 threads
    double w = 0.0;
    if (t < NB) {
        double it = g_inter[t], un = g_union[t];
        w = 1.0 - (2.0 * it + 0.5) / (un + 0.5);
    }
    #pragma unroll
    for (int o = 16; o; o >>= 1) w += __shfl_down_sync(0xffffffffu, w, o);
    __shared__ double sh[2];
    if ((t & 31) == 0) sh[t >> 5] = w;
    __syncthreads();
    if (t == 0) out[0] = (float)((sh[0] + sh[1]) / (double)NB);
}

extern "C" void kernel_launch(void* const* d_in, const int* in_sizes, int n_in,
                              void* d_out, int out_size) {
    const float* pred = (const float*)d_in[0];
    const float* mask = (const float*)d_in[1];
    float* out = (float*)d_out;

    zero_acc_kernel<<<1, 64>>>();
    vpass_kernel<<<dim3(WW / 256, 4, NB), 256>>>(mask);
    hpass_kernel<<<dim3(HH, NB), 128>>>(pred, mask);
    finalize_kernel<<<1, 64>>>(out);
}